// round 3
// baseline (speedup 1.0000x reference)
#include <cuda_runtime.h>
#include <stdint.h>
#include <math.h>

#define BATCH 32
#define CHAN  256
#define HH    56
#define WW    56
#define S     (HH*WW)       // 3136
#define S4    (S/4)         // 784
#define QSPLIT 8
#define CQ    (CHAN/QSPLIT) // 32
#define RNUM  1568          // removed_num = round(3136*0.5)

// scratch (no cudaMalloc allowed)
__device__ __align__(16) float g_part_max[QSPLIT*BATCH*S];
__device__ __align__(16) float g_part_sum[QSPLIT*BATCH*S];
__device__ __align__(16) float g_y[BATCH*S];

// ---------------------------------------------------------------------------
// Kernel 1: partial channel max/sum. Each thread owns 4 consecutive spatial
// positions (float4) and 32 of the 256 channels. 784 blocks x 256 threads.
// Read-roofline kernel (~103 MB in).
// ---------------------------------------------------------------------------
__global__ void pool_partial(const float* __restrict__ x) {
    int gid = blockIdx.x * blockDim.x + threadIdx.x;
    int q   = gid / (BATCH * S4);
    int rem = gid % (BATCH * S4);
    int b   = rem / S4;
    int s4  = rem % S4;

    const float4* p = reinterpret_cast<const float4*>(x)
                    + (size_t)(b * CHAN + q * CQ) * S4 + s4;

    float4 mx = make_float4(-INFINITY, -INFINITY, -INFINITY, -INFINITY);
    float4 sm = make_float4(0.f, 0.f, 0.f, 0.f);

    #pragma unroll 16
    for (int c = 0; c < CQ; ++c) {
        float4 v = __ldg(p + (size_t)c * S4);
        mx.x = fmaxf(mx.x, v.x); mx.y = fmaxf(mx.y, v.y);
        mx.z = fmaxf(mx.z, v.z); mx.w = fmaxf(mx.w, v.w);
        sm.x += v.x; sm.y += v.y; sm.z += v.z; sm.w += v.w;
    }

    int o = (q * BATCH + b) * S4 + s4;
    reinterpret_cast<float4*>(g_part_max)[o] = mx;
    reinterpret_cast<float4*>(g_part_sum)[o] = sm;
}

// ---------------------------------------------------------------------------
// Kernel 2 (fused): per batch -> combine partials, 3x3 conv + sigmoid,
// exact radix select of RNUM smallest, zero them, write masked map to g_y.
// One block per batch, 1024 threads.
//   - histogram: warp-aggregated atomics (match_any) — sigmoid outputs cluster
//     into 1-2 bins on pass 0, naive atomics serialize badly.
//   - bin prefix: shfl-based warp scans (2 barriers instead of 32).
// ---------------------------------------------------------------------------
__global__ void __launch_bounds__(1024, 1) fused_conv_topk(const float* __restrict__ w) {
    __shared__ float pm[S];                 // pooled max
    __shared__ float pa[S];                 // pooled avg
    __shared__ unsigned int uvals[S];       // sigmoid bits (>0 so uint order == float order)
    __shared__ int hist[256];
    __shared__ int warpTot[8];
    __shared__ float ws[18];
    __shared__ unsigned int s_prefix;
    __shared__ int s_r, s_less;
    __shared__ int tieIdx[256];
    __shared__ int tieCount;

    const int b = blockIdx.x;
    const int t = threadIdx.x;
    const int lane = t & 31;

    if (t < 18) ws[t] = w[t];
    if (t == 0) { s_r = RNUM - 1; s_less = 0; s_prefix = 0u; tieCount = 0; }

    // --- combine QSPLIT partials into pooled max / avg (smem) ---
    const float inv = 1.0f / (float)CHAN;
    for (int i = t; i < S; i += 1024) {
        float mx = -INFINITY, sm = 0.f;
        #pragma unroll
        for (int q = 0; q < QSPLIT; ++q) {
            int o = (q * BATCH + b) * S + i;
            mx = fmaxf(mx, g_part_max[o]);
            sm += g_part_sum[o];
        }
        pm[i] = mx;
        pa[i] = sm * inv;
    }
    __syncthreads();

    // --- 3x3 conv (2ch->1ch, pad 1, cross-correlation OIHW) + sigmoid ---
    for (int i = t; i < S; i += 1024) {
        int oh = i / WW, ow = i % WW;
        float acc = 0.f;
        #pragma unroll
        for (int ky = 0; ky < 3; ++ky) {
            int ih = oh + ky - 1;
            if (ih < 0 || ih >= HH) continue;
            #pragma unroll
            for (int kx = 0; kx < 3; ++kx) {
                int iw = ow + kx - 1;
                if (iw < 0 || iw >= WW) continue;
                int ii = ih * WW + iw;
                acc = fmaf(pm[ii], ws[ky * 3 + kx], acc);
                acc = fmaf(pa[ii], ws[9 + ky * 3 + kx], acc);
            }
        }
        float y = 1.0f / (1.0f + expf(-acc));
        uvals[i] = __float_as_uint(y);
    }
    __syncthreads();

    // --- 4-pass radix select (8 bits/pass) ---
    #pragma unroll
    for (int pass = 0; pass < 4; ++pass) {
        const int shift = 24 - 8 * pass;
        if (t < 256) hist[t] = 0;
        __syncthreads();

        const unsigned int pmask = (pass == 0) ? 0u : (0xFFFFFFFFu << (32 - 8 * pass));
        const unsigned int pref  = s_prefix;

        // padded loop bound (4096) -> every lane does 4 iterations, full-warp
        // participation for match_any; invalid lanes use sentinel key 0x100.
        for (int i = t; i < 4096; i += 1024) {
            unsigned int key = 0x100u;
            if (i < S) {
                unsigned int u = uvals[i];
                if ((u & pmask) == pref) key = (u >> shift) & 0xFFu;
            }
            unsigned int grp = __match_any_sync(0xFFFFFFFFu, key);
            if (key != 0x100u) {
                int leader = __ffs(grp) - 1;
                if (lane == leader) atomicAdd(&hist[key], __popc(grp));
            }
        }
        __syncthreads();

        // inclusive prefix over 256 bins: warp shfl scan + warp-total scan
        int v = 0;
        if (t < 256) {
            v = hist[t];
            #pragma unroll
            for (int d = 1; d < 32; d <<= 1) {
                int n = __shfl_up_sync(0xFFFFFFFFu, v, d);
                if (lane >= d) v += n;
            }
            if (lane == 31) warpTot[t >> 5] = v;
        }
        __syncthreads();
        if (t < 8) {
            int wv = warpTot[t];
            #pragma unroll
            for (int d = 1; d < 8; d <<= 1) {
                int n = __shfl_up_sync(0xFFu, wv, d);
                if (t >= d) wv += n;
            }
            warpTot[t] = wv;
        }
        __syncthreads();
        if (t < 256) {
            int incl = v + ((t >= 32) ? warpTot[(t >> 5) - 1] : 0);
            int excl = incl - hist[t];
            int r = s_r;
            if (excl <= r && r < incl) {           // exactly one bin matches
                s_r      = r - excl;
                s_less  += excl;
                s_prefix = pref | ((unsigned int)t << shift);
            }
        }
        __syncthreads();
    }

    const unsigned int T = s_prefix;        // exact value at rank RNUM-1
    const int zeroTies = RNUM - s_less;     // # of values == T to zero (ascending index)

    float* yb = g_y + b * S;
    for (int i = t; i < S; i += 1024) {
        unsigned int u = uvals[i];
        float v = __uint_as_float(u);
        if (u < T) {
            v = 0.0f;
        } else if (u == T) {
            int p = atomicAdd(&tieCount, 1);
            if (p < 256) tieIdx[p] = i;
        }
        yb[i] = v;
    }
    __syncthreads();

    if (t == 0) {
        int tc = tieCount < 256 ? tieCount : 256;
        for (int i = 1; i < tc; ++i) {       // tiny insertion sort (expected tc==1)
            int v2 = tieIdx[i], j = i - 1;
            while (j >= 0 && tieIdx[j] > v2) { tieIdx[j + 1] = tieIdx[j]; --j; }
            tieIdx[j + 1] = v2;
        }
        int z = zeroTies < tc ? zeroTies : tc;
        for (int j = 0; j < z; ++j) yb[tieIdx[j]] = 0.0f;
    }
}

// ---------------------------------------------------------------------------
// Kernel 3: broadcast masked map to all 256 channels (write-roofline kernel).
// ---------------------------------------------------------------------------
__global__ void bcast(float* __restrict__ out) {
    int gid = blockIdx.x * blockDim.x + threadIdx.x;   // 0 .. BATCH*CHAN*S4-1
    int row = gid / S4;          // b*256 + c
    int s4  = gid % S4;
    int b   = row >> 8;
    float4 v = __ldg(reinterpret_cast<const float4*>(g_y) + b * S4 + s4);
    reinterpret_cast<float4*>(out)[gid] = v;
}

// ---------------------------------------------------------------------------
extern "C" void kernel_launch(void* const* d_in, const int* in_sizes, int n_in,
                              void* d_out, int out_size) {
    const float* x = (const float*)d_in[0];   // [32,256,56,56]
    const float* w = (const float*)d_in[1];   // [1,2,3,3]
    float* out = (float*)d_out;               // [32,256,56,56]

    pool_partial<<<(QSPLIT * BATCH * S4) / 256, 256>>>(x);   // 784 blocks
    fused_conv_topk<<<BATCH, 1024>>>(w);                     // 32 blocks
    bcast<<<(BATCH * CHAN * S4) / 256, 256>>>(out);          // 25088 blocks
}